// round 13
// baseline (speedup 1.0000x reference)
#include <cuda_runtime.h>

#define BLOCK 256
#define EPT 4
#define TILE (BLOCK * EPT)   // 1024 elements per block
#define FULLM 0xffffffffu

__device__ double g_firing;          // zero-initialized at load; restored to 0 each launch
__device__ unsigned int g_count;     // ditto

// Scaled limiter: returns 2*L. Caller folds the 1/2 into COEF2.
__device__ __forceinline__ float limiter2(float a, float b) {
    return fminf(fabsf(a + b), 4.0f * fminf(fabsf(a), fabsf(b)));
}

__device__ __forceinline__ float ex2(float x) {   // raw MUFU EX2 (2^x)
    float r;
    asm("ex2.approx.ftz.f32 %0, %1;" : "=f"(r) : "f"(x));
    return r;
}

__device__ __forceinline__ void stcs4(float* p, float4 v) {   // streaming store (evict-first)
    asm volatile("st.global.cs.v4.f32 [%0], {%1,%2,%3,%4};"
                 :: "l"(p), "f"(v.x), "f"(v.y), "f"(v.z), "f"(v.w) : "memory");
}

// H(V): also returns dVdt via reference.
__device__ __forceinline__ float H_of_V(float vz0, float C1, float C2,
                                        float inv_tau, float& dVdt_out)
{
    // A-poly coefficients pre-multiplied by log2(e)
    constexpr float c0 =  0.0088004397f;
    constexpr float c1 = -1.6158184458f;
    constexpr float c2 = -0.3707726255f;
    constexpr float c3 = -0.1038740429f;
    constexpr float c4 = -0.0168795320f;
    constexpr float NL2E = -1.4426950408889634f; // -log2(e)
    constexpr float ISS  = 0.57735026919f;       // 1/(SIGMA*sqrt(2))
    constexpr float ISSK = 0.6514700193f;        // ISS * SQ2 * SQ2PI

    const float dVdt = fmaf(-C2, vz0, C1);
    dVdt_out = dVdt;

    const float T  = fmaxf(-vz0, -1.0f) * ISS;   // VT = 0
    const float e  = ex2(NL2E * (T * T));        // exp(-T^2)

    // A = exp(p(T))
    const float A  = ex2(fmaf(T, fmaf(T, fmaf(T, fmaf(T, c4, c3), c2), c1), c0));

    // erf(T) ~ sign(T)*(1 - poly(t)*exp(-T^2)),  t = 1/(1 + 0.3275911|T|)
    const float tt = __frcp_rn(fmaf(0.3275911f, fabsf(T), 1.0f));
    float poly = fmaf(tt,  1.061405429f, -1.453152027f);
    poly = fmaf(tt, poly,  1.421413741f);
    poly = fmaf(tt, poly, -0.284496736f);
    poly = fmaf(tt, poly,  0.254829592f);
    poly *= tt;
    const float erfT = copysignf(fmaf(-poly, e, 1.0f), T);

    // H = A*inv_tau + max(dVdt*ISSK,0) * e / (1.00000001 + erf(T))
    const float D  = 1.00000001f + erfT;
    const float G  = fmaxf(dVdt * ISSK, 0.0f);
    const float Bv = G * e * __frcp_rn(D);

    return fmaxf(fmaf(A, inv_tau, Bv), 0.0f);
}

__global__ void __launch_bounds__(BLOCK, 6)   // cap regs at 40 -> 48-warp residency ceiling
main_kernel(const float* __restrict__ y,
            const float* __restrict__ gsyn_p,
            const float* __restrict__ isyn_p,
            float* __restrict__ out,
            int n)
{
    constexpr float GL      = 0.1f;
    constexpr float EL      = -5.0f;
    constexpr float CMI     = 1.0f / 0.3f;       // 1/Cm
    constexpr float IEXT    = 0.4f;
    constexpr float INV_DTS = 2.0f;              // 1/DTS
    constexpr float COEF2   = 0.2f;              // 0.5*(1 - DT/DTS) * 0.5  (limiter2 carries 2x)

    __shared__ float s_red[BLOCK / 32];

    const float* ro = y;
    const float* V  = y + n;

    const float Isyn    = __ldg(isyn_p);
    const float inv_tau = (GL + __ldg(gsyn_p)) * CMI;          // 1/tau_m
    const float C1      = (GL * EL + IEXT + Isyn) * CMI;       // dVdt = C1 - C2*V
    const float C2      = GL * CMI;

    const int t    = threadIdx.x;
    const int lane = t & 31;
    const int i0   = blockIdx.x * TILE + 4 * t;

    float fsum = 0.0f;

    // warp-uniform path selection (needed for convergent shuffles)
    const bool interior = (i0 >= 2) && (i0 + 4 < n);
    if (__all_sync(FULLM, interior)) {
        // ---------- interior fast path: halo via warp shuffle ----------
        const float4 r4 = *reinterpret_cast<const float4*>(ro + i0);
        const float4 v4 = *reinterpret_cast<const float4*>(V + i0);

        // rv[0]=i0-2 (prev lane .z), rv[1]=i0-1 (prev lane .w), rv[6]=i0+4 (next lane .x)
        float rpz = __shfl_up_sync(FULLM, r4.z, 1);
        float rpw = __shfl_up_sync(FULLM, r4.w, 1);
        float rnx = __shfl_down_sync(FULLM, r4.x, 1);
        float vpz = __shfl_up_sync(FULLM, v4.z, 1);
        float vpw = __shfl_up_sync(FULLM, v4.w, 1);
        float vnx = __shfl_down_sync(FULLM, v4.x, 1);
        if (lane == 0) {            // cross-warp seam (2 active lanes per warp)
            rpz = __ldg(ro + i0 - 2); rpw = __ldg(ro + i0 - 1);
            vpz = __ldg(V + i0 - 2);  vpw = __ldg(V + i0 - 1);
        }
        if (lane == 31) {
            rnx = __ldg(ro + i0 + 4);
            vnx = __ldg(V + i0 + 4);
        }

        float rv[7] = { rpz, rpw, r4.x, r4.y, r4.z, r4.w, rnx };
        float vv[7] = { vpz, vpw, v4.x, v4.y, v4.z, v4.w, vnx };

        float rd[6], vd[6];
        #pragma unroll
        for (int k = 0; k < 6; k++) { rd[k] = rv[k + 1] - rv[k]; vd[k] = vv[k + 1] - vv[k]; }
        float rL[5], vL[5];
        #pragma unroll
        for (int k = 0; k < 5; k++) { rL[k] = limiter2(rd[k + 1], rd[k]); vL[k] = limiter2(vd[k + 1], vd[k]); }

        float outr[EPT], outv[EPT];
        #pragma unroll
        for (int j = 0; j < EPT; j++) {
            float dVdt;
            const float Hv = H_of_V(vv[j + 2], C1, C2, inv_tau, dVdt);

            const float srcr = rv[j + 2] * Hv;
            fsum += srcr;

            outr[j] = fmaf(-INV_DTS, fmaf(COEF2, rL[j + 1] - rL[j], rd[j + 1]), -srcr);
            outv[j] = fmaf(-INV_DTS, fmaf(COEF2, vL[j + 1] - vL[j], vd[j + 1]),  dVdt);
        }
        stcs4(out + i0,     make_float4(outr[0], outr[1], outr[2], outr[3]));
        stcs4(out + n + i0, make_float4(outv[0], outv[1], outv[2], outv[3]));
    } else {
        // ---------- boundary slow path (2 edge warps of the grid) ----------
        #pragma unroll
        for (int j = 0; j < EPT; j++) {
            const int i = i0 + j;
            if (i >= n) break;
            const int im2 = max(i - 2, 0), im1 = max(i - 1, 0), ip1 = min(i + 1, n - 1);

            const float rzm2 = __ldg(ro + im2), rzm1 = __ldg(ro + im1);
            const float rz0  = __ldg(ro + i),   rzp1 = __ldg(ro + ip1);
            const float vzm2 = __ldg(V + im2),  vzm1 = __ldg(V + im1);
            const float vz0  = __ldg(V + i),    vzp1 = __ldg(V + ip1);

            float dVdt;
            const float Hv = H_of_V(vz0, C1, C2, inv_tau, dVdt);

            const float srcr = rz0 * Hv;
            fsum += srcr;

            // dro_dt  (out[0] is written exclusively by the last-finishing block)
            {
                float dm2 = rzm1 - rzm2, dm1 = rz0 - rzm1, dd0 = rzp1 - rz0;
                float Lm  = (i >= 2) ? limiter2(dm1, dm2) : 0.0f;
                if (i == n - 1) {
                    out[i] = fmaf(INV_DTS, fmaf(COEF2, Lm, rzm1), -srcr);
                } else if (i != 0) {
                    out[i] = fmaf(-INV_DTS, fmaf(COEF2, limiter2(dd0, dm1) - Lm, dm1), -srcr);
                }
            }
            // dV_dt
            {
                float dm2 = vzm1 - vzm2, dm1 = vz0 - vzm1, dd0 = vzp1 - vz0;
                float Lm  = (i >= 2) ? limiter2(dm1, dm2) : 0.0f;
                float o;
                if (i == 0)           o = 0.0f;
                else if (i == n - 1)  o = dVdt;
                else                  o = fmaf(-INV_DTS, fmaf(COEF2, limiter2(dd0, dm1) - Lm, dm1), dVdt);
                out[n + i] = o;
            }
        }
    }

    // ---------- block reduction of firing ----------
    #pragma unroll
    for (int off = 16; off > 0; off >>= 1)
        fsum += __shfl_down_sync(FULLM, fsum, off);
    if (lane == 0) s_red[t >> 5] = fsum;
    __syncthreads();
    if (t < 32) {
        float v = (t < BLOCK / 32) ? s_red[t] : 0.0f;
        #pragma unroll
        for (int off = 4; off > 0; off >>= 1)
            v += __shfl_down_sync(FULLM, v, off);
        if (t == 0) {
            atomicAdd(&g_firing, (double)v);
            __threadfence();
            unsigned int done = atomicAdd(&g_count, 1u);
            if (done == gridDim.x - 1) {
                __threadfence();
                double f = atomicAdd(&g_firing, 0.0);
                // dro_dt[0] = -ro[0]/DTS - src[0],  src[0] = -firing
                out[0] = fmaf(-2.0f, __ldg(y), (float)f);
                // restore initial state for the next (graph-replayed) call
                atomicExch(&g_count, 0u);
                atomicExch(reinterpret_cast<unsigned long long*>(&g_firing), 0ull);
            }
        }
    }
}

extern "C" void kernel_launch(void* const* d_in, const int* in_sizes, int n_in,
                              void* d_out, int out_size)
{
    // inputs: [0]=t(1), [1]=y(2N), [2]=gsyn(1), [3]=Isyn(1)
    const float* y    = (const float*)d_in[1];
    const float* gsyn = (const float*)d_in[2];
    const float* isyn = (const float*)d_in[3];
    float* out = (float*)d_out;
    const int n = in_sizes[1] / 2;

    const int nblocks = (n + TILE - 1) / TILE;
    main_kernel<<<nblocks, BLOCK>>>(y, gsyn, isyn, out, n);
}

// round 17
// speedup vs baseline: 1.2884x; 1.2884x over previous
#include <cuda_runtime.h>

#define BLOCK 256
#define EPT 4
#define TILE (BLOCK * EPT)   // 1024 elements per block
#define FULLM 0xffffffffu

__device__ double g_firing;          // zero-initialized at load; restored to 0 each launch
__device__ unsigned int g_count;     // ditto

// Scaled limiter: returns 2*L. Caller folds the 1/2 into COEF2.
__device__ __forceinline__ float limiter2(float a, float b) {
    return fminf(fabsf(a + b), 4.0f * fminf(fabsf(a), fabsf(b)));
}

__device__ __forceinline__ float ex2(float x) {   // raw MUFU EX2 (2^x)
    float r;
    asm("ex2.approx.ftz.f32 %0, %1;" : "=f"(r) : "f"(x));
    return r;
}

__device__ __forceinline__ float frcp(float x) {  // raw MUFU RCP (no Newton refine)
    float r;
    asm("rcp.approx.ftz.f32 %0, %1;" : "=f"(r) : "f"(x));
    return r;
}

__device__ __forceinline__ void stcs4(float* p, float4 v) {   // streaming store (evict-first)
    asm volatile("st.global.cs.v4.f32 [%0], {%1,%2,%3,%4};"
                 :: "l"(p), "f"(v.x), "f"(v.y), "f"(v.z), "f"(v.w) : "memory");
}

// H(V): also returns dVdt via reference.
__device__ __forceinline__ float H_of_V(float vz0, float C1, float C2,
                                        float inv_tau, float& dVdt_out)
{
    // A-poly coefficients pre-multiplied by log2(e)
    constexpr float c0 =  0.0088004397f;
    constexpr float c1 = -1.6158184458f;
    constexpr float c2 = -0.3707726255f;
    constexpr float c3 = -0.1038740429f;
    constexpr float c4 = -0.0168795320f;
    constexpr float NL2E = -1.4426950408889634f; // -log2(e)
    constexpr float ISS  = 0.57735026919f;       // 1/(SIGMA*sqrt(2))
    constexpr float ISSK = 0.6514700193f;        // ISS * SQ2 * SQ2PI

    const float dVdt = fmaf(-C2, vz0, C1);
    dVdt_out = dVdt;

    const float T  = fmaxf(-vz0, -1.0f) * ISS;   // VT = 0
    const float e  = ex2(NL2E * (T * T));        // exp(-T^2)

    // A = exp(p(T))
    const float A  = ex2(fmaf(T, fmaf(T, fmaf(T, fmaf(T, c4, c3), c2), c1), c0));

    // erf(T) ~ sign(T)*(1 - poly(t)*exp(-T^2)),  t = 1/(1 + 0.3275911|T|)
    const float tt = frcp(fmaf(0.3275911f, fabsf(T), 1.0f));
    float poly = fmaf(tt,  1.061405429f, -1.453152027f);
    poly = fmaf(tt, poly,  1.421413741f);
    poly = fmaf(tt, poly, -0.284496736f);
    poly = fmaf(tt, poly,  0.254829592f);
    poly *= tt;
    const float erfT = copysignf(fmaf(-poly, e, 1.0f), T);

    // H = A*inv_tau + max(dVdt*ISSK,0) * e / (1.00000001 + erf(T))
    const float D  = 1.00000001f + erfT;
    const float G  = fmaxf(dVdt * ISSK, 0.0f);
    const float Bv = G * e * frcp(D);

    return fmaxf(fmaf(A, inv_tau, Bv), 0.0f);
}

__global__ void __launch_bounds__(BLOCK, 7)   // target 36 regs -> 56-warp residency ceiling
main_kernel(const float* __restrict__ y,
            const float* __restrict__ gsyn_p,
            const float* __restrict__ isyn_p,
            float* __restrict__ out,
            int n)
{
    constexpr float GL      = 0.1f;
    constexpr float EL      = -5.0f;
    constexpr float CMI     = 1.0f / 0.3f;       // 1/Cm
    constexpr float IEXT    = 0.4f;
    constexpr float INV_DTS = 2.0f;              // 1/DTS
    constexpr float COEF2   = 0.2f;              // 0.5*(1 - DT/DTS) * 0.5  (limiter2 carries 2x)

    __shared__ float s_red[BLOCK / 32];

    const float* ro = y;
    const float* V  = y + n;

    const float Isyn    = __ldg(isyn_p);
    const float inv_tau = (GL + __ldg(gsyn_p)) * CMI;          // 1/tau_m
    const float C1      = (GL * EL + IEXT + Isyn) * CMI;       // dVdt = C1 - C2*V
    const float C2      = GL * CMI;

    const int t  = threadIdx.x;
    const int i0 = blockIdx.x * TILE + 4 * t;

    float fsum = 0.0f;

    if (i0 >= 2 && i0 + 4 < n) {
        // ---------- interior fast path (branch-free) ----------
        float rv[7], vv[7];
        const float4 r4 = *reinterpret_cast<const float4*>(ro + i0);
        const float4 v4 = *reinterpret_cast<const float4*>(V + i0);
        rv[0] = __ldg(ro + i0 - 2); rv[1] = __ldg(ro + i0 - 1);
        rv[2] = r4.x; rv[3] = r4.y; rv[4] = r4.z; rv[5] = r4.w;
        rv[6] = __ldg(ro + i0 + 4);
        vv[0] = __ldg(V + i0 - 2);  vv[1] = __ldg(V + i0 - 1);
        vv[2] = v4.x; vv[3] = v4.y; vv[4] = v4.z; vv[5] = v4.w;
        vv[6] = __ldg(V + i0 + 4);

        float rd[6], vd[6];
        #pragma unroll
        for (int k = 0; k < 6; k++) { rd[k] = rv[k + 1] - rv[k]; vd[k] = vv[k + 1] - vv[k]; }
        float rL[5], vL[5];
        #pragma unroll
        for (int k = 0; k < 5; k++) { rL[k] = limiter2(rd[k + 1], rd[k]); vL[k] = limiter2(vd[k + 1], vd[k]); }

        float outr[EPT], outv[EPT];
        #pragma unroll
        for (int j = 0; j < EPT; j++) {
            float dVdt;
            const float Hv = H_of_V(vv[j + 2], C1, C2, inv_tau, dVdt);

            const float srcr = rv[j + 2] * Hv;
            fsum += srcr;

            outr[j] = fmaf(-INV_DTS, fmaf(COEF2, rL[j + 1] - rL[j], rd[j + 1]), -srcr);
            outv[j] = fmaf(-INV_DTS, fmaf(COEF2, vL[j + 1] - vL[j], vd[j + 1]),  dVdt);
        }
        stcs4(out + i0,     make_float4(outr[0], outr[1], outr[2], outr[3]));
        stcs4(out + n + i0, make_float4(outv[0], outv[1], outv[2], outv[3]));
    } else {
        // ---------- boundary slow path (first/last blocks only) ----------
        #pragma unroll
        for (int j = 0; j < EPT; j++) {
            const int i = i0 + j;
            if (i >= n) break;
            const int im2 = max(i - 2, 0), im1 = max(i - 1, 0), ip1 = min(i + 1, n - 1);

            const float rzm2 = __ldg(ro + im2), rzm1 = __ldg(ro + im1);
            const float rz0  = __ldg(ro + i),   rzp1 = __ldg(ro + ip1);
            const float vzm2 = __ldg(V + im2),  vzm1 = __ldg(V + im1);
            const float vz0  = __ldg(V + i),    vzp1 = __ldg(V + ip1);

            float dVdt;
            const float Hv = H_of_V(vz0, C1, C2, inv_tau, dVdt);

            const float srcr = rz0 * Hv;
            fsum += srcr;

            // dro_dt  (out[0] is written exclusively by the last-finishing block)
            {
                float dm2 = rzm1 - rzm2, dm1 = rz0 - rzm1, dd0 = rzp1 - rz0;
                float Lm  = (i >= 2) ? limiter2(dm1, dm2) : 0.0f;
                if (i == n - 1) {
                    out[i] = fmaf(INV_DTS, fmaf(COEF2, Lm, rzm1), -srcr);
                } else if (i != 0) {
                    out[i] = fmaf(-INV_DTS, fmaf(COEF2, limiter2(dd0, dm1) - Lm, dm1), -srcr);
                }
            }
            // dV_dt
            {
                float dm2 = vzm1 - vzm2, dm1 = vz0 - vzm1, dd0 = vzp1 - vz0;
                float Lm  = (i >= 2) ? limiter2(dm1, dm2) : 0.0f;
                float o;
                if (i == 0)           o = 0.0f;
                else if (i == n - 1)  o = dVdt;
                else                  o = fmaf(-INV_DTS, fmaf(COEF2, limiter2(dd0, dm1) - Lm, dm1), dVdt);
                out[n + i] = o;
            }
        }
    }

    // ---------- block reduction of firing ----------
    #pragma unroll
    for (int off = 16; off > 0; off >>= 1)
        fsum += __shfl_down_sync(FULLM, fsum, off);
    if ((t & 31) == 0) s_red[t >> 5] = fsum;
    __syncthreads();
    if (t < 32) {
        float v = (t < BLOCK / 32) ? s_red[t] : 0.0f;
        #pragma unroll
        for (int off = 4; off > 0; off >>= 1)
            v += __shfl_down_sync(FULLM, v, off);
        if (t == 0) {
            atomicAdd(&g_firing, (double)v);
            __threadfence();
            unsigned int done = atomicAdd(&g_count, 1u);
            if (done == gridDim.x - 1) {
                __threadfence();
                double f = atomicAdd(&g_firing, 0.0);
                // dro_dt[0] = -ro[0]/DTS - src[0],  src[0] = -firing
                out[0] = fmaf(-2.0f, __ldg(y), (float)f);
                // restore initial state for the next (graph-replayed) call
                atomicExch(&g_count, 0u);
                atomicExch(reinterpret_cast<unsigned long long*>(&g_firing), 0ull);
            }
        }
    }
}

extern "C" void kernel_launch(void* const* d_in, const int* in_sizes, int n_in,
                              void* d_out, int out_size)
{
    // inputs: [0]=t(1), [1]=y(2N), [2]=gsyn(1), [3]=Isyn(1)
    const float* y    = (const float*)d_in[1];
    const float* gsyn = (const float*)d_in[2];
    const float* isyn = (const float*)d_in[3];
    float* out = (float*)d_out;
    const int n = in_sizes[1] / 2;

    const int nblocks = (n + TILE - 1) / TILE;
    main_kernel<<<nblocks, BLOCK>>>(y, gsyn, isyn, out, n);
}